// round 8
// baseline (speedup 1.0000x reference)
#include <cuda_runtime.h>
#include <cuda_fp16.h>
#include <cstdint>
#include <cstddef>

// ----- problem constants -----
#define LSITES  784
#define CHI     128
#define BATCH   1024
#define NCLS    10
#define WROW    264               // padded k-stride of transposed W (halves)
#define SITE_HALVES (CHI * WROW)  // 33792 halves per site
#define SITE_BYTES  (SITE_HALVES * 2)  // 67584 B per site
#define BC      16                // samples per CTA
#define NCTA    (BATCH / BC)      // 64
#define THREADS 512
#define HROW    132               // classifier h row stride (floats)
#define AROW    136               // padded A row stride (halves), K=128
#define ABUF_HALVES (BC * AROW)   // 2176 halves
#define ABUF_BYTES  (ABUF_HALVES * 2)   // 4352
#define DROW    132               // Dbuf row stride (floats)
#define DBUF_BYTES (BC * DROW * 4)      // 8448
#define SMEM_A_OFF   (2 * SITE_BYTES)              // 135168
#define SMEM_D_OFF   (SMEM_A_OFF + 2 * ABUF_BYTES) // 143872
#define SMEM_MB_OFF  (SMEM_D_OFF + DBUF_BYTES)     // 152320
#define SMEM_TOTAL   (SMEM_MB_OFF + 16)            // 152336

// fp16 transposed weights: Wt[site][b][k], k = s*128 + a, row stride WROW
__device__ __half g_Wt[(size_t)LSITES * SITE_HALVES];   // ~50.5 MB static scratch

// ---------------------------------------------------------------------------
// Prepass: W fp32 [n][s][a][b]  ->  fp16 Wt [n][b][k=s*128+a], padded rows
// ---------------------------------------------------------------------------
__global__ void __launch_bounds__(256) prep_kernel(const float* __restrict__ W) {
    extern __shared__ __half sw[];   // [256][132] halves
    const int n   = blockIdx.x;
    const int tid = threadIdx.x;
    const float* Wg = W + (size_t)n * (2 * CHI * CHI);

    for (int i = 0; i < 128; ++i) {
        int e = i * 256 + tid;
        int k = e >> 7;
        int b = e & 127;
        sw[k * 132 + b] = __float2half_rn(Wg[e]);
    }
    __syncthreads();

    const int w    = tid >> 5;
    const int lane = tid & 31;
    for (int r = 0; r < 16; ++r) {
        int b  = w * 16 + r;
        int k0 = lane * 8;
        __align__(16) __half tmp[8];
#pragma unroll
        for (int j = 0; j < 8; ++j) tmp[j] = sw[(k0 + j) * 132 + b];
        *(uint4*)(&g_Wt[((size_t)n * CHI + b) * WROW + k0]) = *(uint4*)tmp;
    }
}

// ---------------------------------------------------------------------------
__device__ __forceinline__ void mbar_wait(uint32_t mbar, uint32_t parity) {
    asm volatile(
        "{\n\t.reg .pred P;\n"
        "W%=:\n\t"
        "mbarrier.try_wait.parity.acquire.cta.shared::cta.b64 P, [%0], %1, 0x989680;\n\t"
        "@!P bra W%=;\n\t}"
        :: "r"(mbar), "r"(parity) : "memory");
}

// ---------------------------------------------------------------------------
// Main kernel: 512 threads, K-split warpgroups, register-resident h (kg=0),
// fp16 mma.sync, one smem partial-exchange + 2 barriers per site.
// ---------------------------------------------------------------------------
__global__ void __launch_bounds__(THREADS, 1) mps_kernel(const float* __restrict__ x,
                                                         const float* __restrict__ V,
                                                         float* __restrict__ out) {
    extern __shared__ char smem[];
    __half* Wbuf = (__half*)smem;                     // [2][SITE_HALVES]
    __half* Abuf = (__half*)(smem + SMEM_A_OFF);      // [2][BC][AROW] fp16(h)
    float*  Dbuf = (float*)(smem + SMEM_D_OFF);       // [BC][DROW] kg=1 partials
    const uint32_t mb = (uint32_t)__cvta_generic_to_shared(smem + SMEM_MB_OFF);

    const int tid  = threadIdx.x;
    const int cta  = blockIdx.x;
    const int kg   = tid >> 8;               // k-group: a in [64*kg, 64*kg+64)
    const int wt   = tid & 255;
    const int w    = wt >> 5;                // warp 0..7 -> cols [w*16, w*16+16)
    const int lane = tid & 31;
    const int g    = lane >> 2;              // 0..7
    const int tg   = lane & 3;               // 0..3
    const int c0   = w * 16 + 2 * tg;        // owned delta column base

    // h registers (kg=0 only; layout matches acc fragments):
    //  h[0]=H[g][c0]   h[1]=H[g][c0+1]   h[2]=H[g+8][c0]   h[3]=H[g+8][c0+1]
    //  h[4]=H[g][c0+8] h[5]=H[g][c0+9]   h[6]=H[g+8][c0+8] h[7]=H[g+8][c0+9]
    float h[8];
#pragma unroll
    for (int i = 0; i < 8; ++i) h[i] = 1.0f;

    if (tid == 0) {
        asm volatile("mbarrier.init.shared.b64 [%0], 1;" :: "r"(mb)     : "memory");
        asm volatile("mbarrier.init.shared.b64 [%0], 1;" :: "r"(mb + 8) : "memory");
    }
    // init Abuf[0] = fp16(1)
    {
        const __half one = __float2half_rn(1.f);
        for (int i = tid; i < ABUF_HALVES; i += THREADS) Abuf[i] = one;
    }
    __syncthreads();

    const uint32_t wbuf_s = (uint32_t)__cvta_generic_to_shared(Wbuf);
    const uint32_t abuf_s = (uint32_t)__cvta_generic_to_shared(Abuf);

    // prologue: stage site 0 into W buffer 0
    if (tid == 0) {
        asm volatile("mbarrier.arrive.expect_tx.shared.b64 _, [%0], %1;"
                     :: "r"(mb), "r"((uint32_t)SITE_BYTES) : "memory");
        asm volatile(
            "cp.async.bulk.shared::cluster.global.mbarrier::complete_tx::bytes [%0], [%1], %2, [%3];"
            :: "r"(wbuf_s), "l"((const void*)g_Wt), "r"((uint32_t)SITE_BYTES), "r"(mb)
            : "memory");
    }

    // per-thread x streams: samples cta*16+g and cta*16+g+8, both features
    const int sg0 = cta * BC + g;
    const int sg1 = sg0 + 8;
    const float* px00 = x + ((size_t)sg0 * 2 + 0) * LSITES;
    const float* px01 = x + ((size_t)sg0 * 2 + 1) * LSITES;
    const float* px10 = x + ((size_t)sg1 * 2 + 0) * LSITES;
    const float* px11 = x + ((size_t)sg1 * 2 + 1) * LSITES;
    float cx00 = __ldg(px00), cx01 = __ldg(px01);
    float cx10 = __ldg(px10), cx11 = __ldg(px11);

    // ldmatrix lane addresses (this k-group's 64-wide a-slice)
    const uint32_t a_base = abuf_s +
        (uint32_t)((((lane & 15) * AROW) + ((lane >> 4) * 8) + kg * 64) * 2);
    const int grp = lane >> 3;
    const int r8  = lane & 7;
    const int bn  = w * 16 + ((grp & 2) ? 8 : 0) + r8;
    const int bk  = (grp & 1) ? 8 : 0;
    const uint32_t b_base = wbuf_s + (uint32_t)((bn * WROW + bk + kg * 64) * 2);

    uint32_t phW0 = 0, phW1 = 0;

    for (int n = 0; n < LSITES; ++n) {
        const int p = n & 1;

        // stage site n+1 into the other W buffer
        if (tid == 0 && n + 1 < LSITES) {
            const uint32_t mnext = mb + (uint32_t)((1 - p) * 8);
            asm volatile("mbarrier.arrive.expect_tx.shared.b64 _, [%0], %1;"
                         :: "r"(mnext), "r"((uint32_t)SITE_BYTES) : "memory");
            asm volatile(
                "cp.async.bulk.shared::cluster.global.mbarrier::complete_tx::bytes [%0], [%1], %2, [%3];"
                :: "r"(wbuf_s + (uint32_t)((1 - p) * SITE_BYTES)),
                   "l"((const void*)(g_Wt + (size_t)(n + 1) * SITE_HALVES)),
                   "r"((uint32_t)SITE_BYTES), "r"(mnext)
                : "memory");
        }

        // prefetch x for next site
        float nx00 = 0.f, nx01 = 0.f, nx10 = 0.f, nx11 = 0.f;
        if (n + 1 < LSITES) {
            nx00 = __ldg(px00 + n + 1); nx01 = __ldg(px01 + n + 1);
            nx10 = __ldg(px10 + n + 1); nx11 = __ldg(px11 + n + 1);
        }

        // A fragments: this k-group's 4 chunks of fp16(h), shared by both features
        uint32_t a[4][4];
        {
            const uint32_t ab = a_base + (uint32_t)(p * ABUF_BYTES);
#pragma unroll
            for (int jj = 0; jj < 4; ++jj) {
                asm volatile(
                    "ldmatrix.sync.aligned.m8n8.x4.shared.b16 {%0,%1,%2,%3}, [%4];\n"
                    : "=r"(a[jj][0]), "=r"(a[jj][1]), "=r"(a[jj][2]), "=r"(a[jj][3])
                    : "r"(ab + (uint32_t)(jj * 32)));
            }
        }

        // wait for this site's W buffer
        mbar_wait(mb + (uint32_t)(p * 8), p ? phW1 : phW0);
        if (p) phW1 ^= 1; else phW0 ^= 1;

        // per-feature partial GEMMs over this k-group's a-slice
        // acc chains: 2 features x 2 n-tiles = 4 chains of depth 4
        float acc0[8], acc1[8];
#pragma unroll
        for (int i = 0; i < 8; ++i) { acc0[i] = 0.f; acc1[i] = 0.f; }
        {
            const uint32_t bl = b_base + (uint32_t)(p * SITE_BYTES);
#pragma unroll
            for (int s = 0; s < 2; ++s) {
                float* acc = s ? acc1 : acc0;
#pragma unroll
                for (int jj = 0; jj < 4; ++jj) {
                    uint32_t b0, b1, b2, b3;
                    asm volatile(
                        "ldmatrix.sync.aligned.m8n8.x4.shared.b16 {%0,%1,%2,%3}, [%4];\n"
                        : "=r"(b0), "=r"(b1), "=r"(b2), "=r"(b3)
                        : "r"(bl + (uint32_t)((s * 128 + jj * 16) * 2)));
                    asm volatile(
                        "mma.sync.aligned.m16n8k16.row.col.f32.f16.f16.f32 "
                        "{%0,%1,%2,%3}, {%4,%5,%6,%7}, {%8,%9}, {%0,%1,%2,%3};\n"
                        : "+f"(acc[0]), "+f"(acc[1]), "+f"(acc[2]), "+f"(acc[3])
                        : "r"(a[jj][0]), "r"(a[jj][1]), "r"(a[jj][2]), "r"(a[jj][3]),
                          "r"(b0), "r"(b1));
                    asm volatile(
                        "mma.sync.aligned.m16n8k16.row.col.f32.f16.f16.f32 "
                        "{%0,%1,%2,%3}, {%4,%5,%6,%7}, {%8,%9}, {%0,%1,%2,%3};\n"
                        : "+f"(acc[4]), "+f"(acc[5]), "+f"(acc[6]), "+f"(acc[7])
                        : "r"(a[jj][0]), "r"(a[jj][1]), "r"(a[jj][2]), "r"(a[jj][3]),
                          "r"(b2), "r"(b3));
                }
            }
        }

        // per-element x-scaled partial: part = x0[row]*acc0 + x1[row]*acc1
        float part[8];
        part[0] = cx00 * acc0[0] + cx01 * acc1[0];
        part[1] = cx00 * acc0[1] + cx01 * acc1[1];
        part[2] = cx10 * acc0[2] + cx11 * acc1[2];
        part[3] = cx10 * acc0[3] + cx11 * acc1[3];
        part[4] = cx00 * acc0[4] + cx01 * acc1[4];
        part[5] = cx00 * acc0[5] + cx01 * acc1[5];
        part[6] = cx10 * acc0[6] + cx11 * acc1[6];
        part[7] = cx10 * acc0[7] + cx11 * acc1[7];
        cx00 = nx00; cx01 = nx01; cx10 = nx10; cx11 = nx11;

        if (kg == 1) {
            // producer: store partials, arrive (non-blocking), then full bar
            float* d0 = Dbuf + g * DROW + c0;
            float* d1 = Dbuf + (g + 8) * DROW + c0;
            *(float2*)(d0)     = make_float2(part[0], part[1]);
            *(float2*)(d1)     = make_float2(part[2], part[3]);
            *(float2*)(d0 + 8) = make_float2(part[4], part[5]);
            *(float2*)(d1 + 8) = make_float2(part[6], part[7]);
            asm volatile("bar.arrive 1, %0;" :: "n"(THREADS) : "memory");
        } else {
            // consumer: wait producers, fold, publish fp16(h) for next site
            asm volatile("bar.sync 1, %0;" :: "n"(THREADS) : "memory");
            const float* d0 = Dbuf + g * DROW + c0;
            const float* d1 = Dbuf + (g + 8) * DROW + c0;
            float2 q0 = *(const float2*)(d0);
            float2 q1 = *(const float2*)(d1);
            float2 q2 = *(const float2*)(d0 + 8);
            float2 q3 = *(const float2*)(d1 + 8);
            h[0] += part[0] + q0.x;  h[1] += part[1] + q0.y;
            h[2] += part[2] + q1.x;  h[3] += part[3] + q1.y;
            h[4] += part[4] + q2.x;  h[5] += part[5] + q2.y;
            h[6] += part[6] + q3.x;  h[7] += part[7] + q3.y;

            if (n + 1 < LSITES) {
                __half* ad = Abuf + (1 - p) * ABUF_HALVES;
                *(__half2*)(ad + g * AROW + c0)           = __floats2half2_rn(h[0], h[1]);
                *(__half2*)(ad + g * AROW + c0 + 8)       = __floats2half2_rn(h[4], h[5]);
                *(__half2*)(ad + (g + 8) * AROW + c0)     = __floats2half2_rn(h[2], h[3]);
                *(__half2*)(ad + (g + 8) * AROW + c0 + 8) = __floats2half2_rn(h[6], h[7]);
            }
        }
        __syncthreads();
    }

    // dump h to smem (reuse Wbuf region) for the classifier
    float* Fh = (float*)smem;   // [16][HROW]
    if (kg == 0) {
        Fh[g * HROW + c0]           = h[0];
        Fh[g * HROW + c0 + 1]       = h[1];
        Fh[g * HROW + c0 + 8]       = h[4];
        Fh[g * HROW + c0 + 9]       = h[5];
        Fh[(g + 8) * HROW + c0]     = h[2];
        Fh[(g + 8) * HROW + c0 + 1] = h[3];
        Fh[(g + 8) * HROW + c0 + 8] = h[6];
        Fh[(g + 8) * HROW + c0 + 9] = h[7];
    }
    __syncthreads();

    // classifier: logits = h @ V  (16 samples x 10 classes per CTA)
    if (tid < BC * NCLS) {
        int r = tid / NCLS, c = tid % NCLS;
        const float* hr = Fh + r * HROW;
        float s = 0.f;
#pragma unroll 8
        for (int a = 0; a < CHI; ++a) s += hr[a] * __ldg(V + a * NCLS + c);
        out[(size_t)(cta * BC + r) * NCLS + c] = s;
    }
}

// ---------------------------------------------------------------------------
extern "C" void kernel_launch(void* const* d_in, const int* in_sizes, int n_in,
                              void* d_out, int out_size) {
    const float* x = nullptr;  // 1024*2*784    = 1605632
    const float* W = nullptr;  // 784*2*128*128 = 25690112
    const float* V = nullptr;  // 128*10        = 1280
    for (int i = 0; i < n_in; ++i) {
        if (in_sizes[i] == BATCH * 2 * LSITES)            x = (const float*)d_in[i];
        else if (in_sizes[i] == LSITES * 2 * CHI * CHI)   W = (const float*)d_in[i];
        else if (in_sizes[i] == CHI * NCLS)               V = (const float*)d_in[i];
    }
    float* out = (float*)d_out;

    static_assert(SMEM_TOTAL == 152336, "smem layout");

    cudaFuncSetAttribute(prep_kernel, cudaFuncAttributeMaxDynamicSharedMemorySize, SITE_BYTES);
    cudaFuncSetAttribute(mps_kernel,  cudaFuncAttributeMaxDynamicSharedMemorySize, SMEM_TOTAL);

    prep_kernel<<<LSITES, 256, SITE_BYTES>>>(W);
    mps_kernel<<<NCTA, THREADS, SMEM_TOTAL>>>(x, V, out);
    (void)out_size;
}

// round 9
// speedup vs baseline: 1.4829x; 1.4829x over previous
#include <cuda_runtime.h>
#include <cuda_fp16.h>
#include <cstdint>
#include <cstddef>

// ----- problem constants -----
#define LSITES  784
#define CHI     128
#define BATCH   1024
#define NCLS    10
#define WROW    264               // padded k-stride of transposed W (halves)
#define SITE_HALVES (CHI * WROW)  // 33792 halves per site
#define SITE_BYTES  (SITE_HALVES * 2)  // 67584 B per site
#define BC      16                // samples per CTA
#define NCTA    (BATCH / BC)      // 64
#define THREADS 512
#define HROW    132               // classifier h row stride (floats)
#define AROW    136               // padded A row stride (halves), K=128
#define ABUF_HALVES (BC * AROW)   // 2176 halves
#define ABUF_BYTES  (ABUF_HALVES * 2)   // 4352
#define SMEM_A_OFF   (2 * SITE_BYTES)               // 135168
#define SMEM_MB_OFF  (SMEM_A_OFF + 2 * ABUF_BYTES)  // 143872
#define SMEM_TOTAL   (SMEM_MB_OFF + 16)             // 143888

// fp16 transposed weights: Wt[site][b][k], k = s*128 + a, row stride WROW
__device__ __half g_Wt[(size_t)LSITES * SITE_HALVES];   // ~50.5 MB static scratch

// ---------------------------------------------------------------------------
// Prepass: W fp32 [n][s][a][b]  ->  fp16 Wt [n][b][k=s*128+a], padded rows
// ---------------------------------------------------------------------------
__global__ void __launch_bounds__(256) prep_kernel(const float* __restrict__ W) {
    extern __shared__ __half sw[];   // [256][132] halves
    const int n   = blockIdx.x;
    const int tid = threadIdx.x;
    const float* Wg = W + (size_t)n * (2 * CHI * CHI);

    for (int i = 0; i < 128; ++i) {
        int e = i * 256 + tid;
        int k = e >> 7;
        int b = e & 127;
        sw[k * 132 + b] = __float2half_rn(Wg[e]);
    }
    __syncthreads();

    const int w    = tid >> 5;
    const int lane = tid & 31;
    for (int r = 0; r < 16; ++r) {
        int b  = w * 16 + r;
        int k0 = lane * 8;
        __align__(16) __half tmp[8];
#pragma unroll
        for (int j = 0; j < 8; ++j) tmp[j] = sw[(k0 + j) * 132 + b];
        *(uint4*)(&g_Wt[((size_t)n * CHI + b) * WROW + k0]) = *(uint4*)tmp;
    }
}

// ---------------------------------------------------------------------------
__device__ __forceinline__ void mbar_wait(uint32_t mbar, uint32_t parity) {
    asm volatile(
        "{\n\t.reg .pred P;\n"
        "W%=:\n\t"
        "mbarrier.try_wait.parity.acquire.cta.shared::cta.b64 P, [%0], %1, 0x989680;\n\t"
        "@!P bra W%=;\n\t}"
        :: "r"(mbar), "r"(parity) : "memory");
}

// ---------------------------------------------------------------------------
// Main kernel: 512 threads, 16 warps, N-split (8 cols/warp), register-resident
// h, fp16 mma.sync, one __syncthreads per site. No cross-warp dependencies.
// ---------------------------------------------------------------------------
__global__ void __launch_bounds__(THREADS, 1) mps_kernel(const float* __restrict__ x,
                                                         const float* __restrict__ V,
                                                         float* __restrict__ out) {
    extern __shared__ char smem[];
    __half* Wbuf = (__half*)smem;                     // [2][SITE_HALVES]
    __half* Abuf = (__half*)(smem + SMEM_A_OFF);      // [2][BC][AROW] fp16(h)
    const uint32_t mb = (uint32_t)__cvta_generic_to_shared(smem + SMEM_MB_OFF);

    const int tid  = threadIdx.x;
    const int cta  = blockIdx.x;
    const int w    = tid >> 5;               // warp 0..15 -> cols [w*8, w*8+8)
    const int lane = tid & 31;
    const int g    = lane >> 2;              // 0..7
    const int tg   = lane & 3;               // 0..3
    const int c0   = w * 8 + 2 * tg;         // owned h/delta column base

    // h registers (m16n8 acc layout):
    //  h[0]=H[g][c0]  h[1]=H[g][c0+1]  h[2]=H[g+8][c0]  h[3]=H[g+8][c0+1]
    float h[4] = {1.f, 1.f, 1.f, 1.f};

    if (tid == 0) {
        asm volatile("mbarrier.init.shared.b64 [%0], 1;" :: "r"(mb)     : "memory");
        asm volatile("mbarrier.init.shared.b64 [%0], 1;" :: "r"(mb + 8) : "memory");
    }
    // init Abuf[0] = fp16(1)
    {
        const __half one = __float2half_rn(1.f);
        for (int i = tid; i < ABUF_HALVES; i += THREADS) Abuf[i] = one;
    }
    __syncthreads();

    const uint32_t wbuf_s = (uint32_t)__cvta_generic_to_shared(Wbuf);
    const uint32_t abuf_s = (uint32_t)__cvta_generic_to_shared(Abuf);

    // prologue: stage site 0 into W buffer 0
    if (tid == 0) {
        asm volatile("mbarrier.arrive.expect_tx.shared.b64 _, [%0], %1;"
                     :: "r"(mb), "r"((uint32_t)SITE_BYTES) : "memory");
        asm volatile(
            "cp.async.bulk.shared::cluster.global.mbarrier::complete_tx::bytes [%0], [%1], %2, [%3];"
            :: "r"(wbuf_s), "l"((const void*)g_Wt), "r"((uint32_t)SITE_BYTES), "r"(mb)
            : "memory");
    }

    // per-thread x streams: samples cta*16+g and cta*16+g+8, both features
    const int sg0 = cta * BC + g;
    const int sg1 = sg0 + 8;
    const float* px00 = x + ((size_t)sg0 * 2 + 0) * LSITES;
    const float* px01 = x + ((size_t)sg0 * 2 + 1) * LSITES;
    const float* px10 = x + ((size_t)sg1 * 2 + 0) * LSITES;
    const float* px11 = x + ((size_t)sg1 * 2 + 1) * LSITES;
    float cx00 = __ldg(px00), cx01 = __ldg(px01);
    float cx10 = __ldg(px10), cx11 = __ldg(px11);

    // ldmatrix lane addresses
    const uint32_t a_base = abuf_s + (uint32_t)((((lane & 15) * AROW) + ((lane >> 4) * 8)) * 2);
    // B x4: 4 tiles = this warp's 8 n-rows, k offsets +0,+8,+16,+24
    const int grp = lane >> 3;               // 0..3 -> k tile
    const int r8  = lane & 7;                // n-row within warp's 8
    const uint32_t b_base = wbuf_s + (uint32_t)(((w * 8 + r8) * WROW + grp * 8) * 2);

    uint32_t phW0 = 0, phW1 = 0;

    for (int n = 0; n < LSITES; ++n) {
        const int p = n & 1;

        // stage site n+1 into the other W buffer
        if (tid == 0 && n + 1 < LSITES) {
            const uint32_t mnext = mb + (uint32_t)((1 - p) * 8);
            asm volatile("mbarrier.arrive.expect_tx.shared.b64 _, [%0], %1;"
                         :: "r"(mnext), "r"((uint32_t)SITE_BYTES) : "memory");
            asm volatile(
                "cp.async.bulk.shared::cluster.global.mbarrier::complete_tx::bytes [%0], [%1], %2, [%3];"
                :: "r"(wbuf_s + (uint32_t)((1 - p) * SITE_BYTES)),
                   "l"((const void*)(g_Wt + (size_t)(n + 1) * SITE_HALVES)),
                   "r"((uint32_t)SITE_BYTES), "r"(mnext)
                : "memory");
        }

        // prefetch x for next site
        float nx00 = 0.f, nx01 = 0.f, nx10 = 0.f, nx11 = 0.f;
        if (n + 1 < LSITES) {
            nx00 = __ldg(px00 + n + 1); nx01 = __ldg(px01 + n + 1);
            nx10 = __ldg(px10 + n + 1); nx11 = __ldg(px11 + n + 1);
        }

        // A fragments: 8 k-chunks of fp16(h), shared by both feature GEMMs
        uint32_t a[8][4];
        {
            const uint32_t ab = a_base + (uint32_t)(p * ABUF_BYTES);
#pragma unroll
            for (int ca = 0; ca < 8; ++ca) {
                asm volatile(
                    "ldmatrix.sync.aligned.m8n8.x4.shared.b16 {%0,%1,%2,%3}, [%4];\n"
                    : "=r"(a[ca][0]), "=r"(a[ca][1]), "=r"(a[ca][2]), "=r"(a[ca][3])
                    : "r"(ab + (uint32_t)(ca * 32)));
            }
        }

        // wait for this site's W buffer
        mbar_wait(mb + (uint32_t)(p * 8), p ? phW1 : phW0);
        if (p) phW1 ^= 1; else phW0 ^= 1;

        // two feature GEMMs, this warp's n8 tile; 4 chains of depth 4
        float acc[4][4];
#pragma unroll
        for (int i = 0; i < 4; ++i)
#pragma unroll
            for (int jj = 0; jj < 4; ++jj) acc[i][jj] = 0.f;
        {
            const uint32_t bl = b_base + (uint32_t)(p * SITE_BYTES);
#pragma unroll
            for (int s = 0; s < 2; ++s) {
#pragma unroll
                for (int j = 0; j < 4; ++j) {
                    float* ac = acc[s * 2 + (j >> 1)];
                    uint32_t b0, b1, b2, b3;
                    asm volatile(
                        "ldmatrix.sync.aligned.m8n8.x4.shared.b16 {%0,%1,%2,%3}, [%4];\n"
                        : "=r"(b0), "=r"(b1), "=r"(b2), "=r"(b3)
                        : "r"(bl + (uint32_t)((s * 128 + j * 32) * 2)));
                    asm volatile(
                        "mma.sync.aligned.m16n8k16.row.col.f32.f16.f16.f32 "
                        "{%0,%1,%2,%3}, {%4,%5,%6,%7}, {%8,%9}, {%0,%1,%2,%3};\n"
                        : "+f"(ac[0]), "+f"(ac[1]), "+f"(ac[2]), "+f"(ac[3])
                        : "r"(a[2*j][0]), "r"(a[2*j][1]), "r"(a[2*j][2]), "r"(a[2*j][3]),
                          "r"(b0), "r"(b1));
                    asm volatile(
                        "mma.sync.aligned.m16n8k16.row.col.f32.f16.f16.f32 "
                        "{%0,%1,%2,%3}, {%4,%5,%6,%7}, {%8,%9}, {%0,%1,%2,%3};\n"
                        : "+f"(ac[0]), "+f"(ac[1]), "+f"(ac[2]), "+f"(ac[3])
                        : "r"(a[2*j+1][0]), "r"(a[2*j+1][1]), "r"(a[2*j+1][2]), "r"(a[2*j+1][3]),
                          "r"(b2), "r"(b3));
                }
            }
        }

        // combine k-half chains, fold with per-row x scalars (f32, registers)
        {
            float f0[4], f1[4];
#pragma unroll
            for (int i = 0; i < 4; ++i) { f0[i] = acc[0][i] + acc[1][i]; f1[i] = acc[2][i] + acc[3][i]; }
            h[0] += cx00 * f0[0] + cx01 * f1[0];
            h[1] += cx00 * f0[1] + cx01 * f1[1];
            h[2] += cx10 * f0[2] + cx11 * f1[2];
            h[3] += cx10 * f0[3] + cx11 * f1[3];
        }
        cx00 = nx00; cx01 = nx01; cx10 = nx10; cx11 = nx11;

        // publish fp16(h) into next site's A buffer
        {
            __half* ad = Abuf + (1 - p) * ABUF_HALVES;
            *(__half2*)(ad + g * AROW + c0)       = __floats2half2_rn(h[0], h[1]);
            *(__half2*)(ad + (g + 8) * AROW + c0) = __floats2half2_rn(h[2], h[3]);
        }
        __syncthreads();
    }

    // dump h to smem (reuse Wbuf region) for the classifier
    float* Fh = (float*)smem;   // [16][HROW]
    Fh[g * HROW + c0]           = h[0];
    Fh[g * HROW + c0 + 1]       = h[1];
    Fh[(g + 8) * HROW + c0]     = h[2];
    Fh[(g + 8) * HROW + c0 + 1] = h[3];
    __syncthreads();

    // classifier: logits = h @ V  (16 samples x 10 classes per CTA)
    if (tid < BC * NCLS) {
        int r = tid / NCLS, c = tid % NCLS;
        const float* hr = Fh + r * HROW;
        float s = 0.f;
#pragma unroll 8
        for (int a = 0; a < CHI; ++a) s += hr[a] * __ldg(V + a * NCLS + c);
        out[(size_t)(cta * BC + r) * NCLS + c] = s;
    }
}

// ---------------------------------------------------------------------------
extern "C" void kernel_launch(void* const* d_in, const int* in_sizes, int n_in,
                              void* d_out, int out_size) {
    const float* x = nullptr;  // 1024*2*784    = 1605632
    const float* W = nullptr;  // 784*2*128*128 = 25690112
    const float* V = nullptr;  // 128*10        = 1280
    for (int i = 0; i < n_in; ++i) {
        if (in_sizes[i] == BATCH * 2 * LSITES)            x = (const float*)d_in[i];
        else if (in_sizes[i] == LSITES * 2 * CHI * CHI)   W = (const float*)d_in[i];
        else if (in_sizes[i] == CHI * NCLS)               V = (const float*)d_in[i];
    }
    float* out = (float*)d_out;

    static_assert(SMEM_TOTAL == 143888, "smem layout");

    cudaFuncSetAttribute(prep_kernel, cudaFuncAttributeMaxDynamicSharedMemorySize, SITE_BYTES);
    cudaFuncSetAttribute(mps_kernel,  cudaFuncAttributeMaxDynamicSharedMemorySize, SMEM_TOTAL);

    prep_kernel<<<LSITES, 256, SITE_BYTES>>>(W);
    mps_kernel<<<NCTA, THREADS, SMEM_TOTAL>>>(x, V, out);
    (void)out_size;
}